// round 7
// baseline (speedup 1.0000x reference)
#include <cuda_runtime.h>
#include <cuda_bf16.h>
#include <cstdint>

// Problem constants
#define NNODE   16384
#define CDIM    48
#define KNN     9
#define BATCHSZ 4096
#define TILE    64

typedef unsigned long long u64;
typedef unsigned int u32;

// -------- scratch (device globals; no allocation allowed) --------
__device__ __align__(256) float g_xf[NNODE * CDIM];   // [N,48] node features
__device__ float g_sq[NNODE];                         // row squared norms
__device__ int   g_nbr[NNODE * KNN];                  // knn indices
__device__ int   g_deg[NNODE];                        // degree over src
__device__ float g_dinv[NNODE];                       // rsqrt(deg)

// packed fp32x2 ops (sm_103a): 2 IEEE fp32 ops per instruction
__device__ __forceinline__ u64 fma2(u64 a, u64 b, u64 c) {
    u64 d;
    asm("fma.rn.f32x2 %0, %1, %2, %3;" : "=l"(d) : "l"(a), "l"(b), "l"(c));
    return d;
}
__device__ __forceinline__ u64 add2(u64 a, u64 b) {
    u64 d;
    asm("add.rn.f32x2 %0, %1, %2;" : "=l"(d) : "l"(a), "l"(b));
    return d;
}
__device__ __forceinline__ void unpack2(u64 v, float& lo, float& hi) {
    asm("mov.b64 {%0, %1}, %2;" : "=f"(lo), "=f"(hi) : "l"(v));
}
__device__ __forceinline__ void cp16(u32 dst_smem, const void* src) {
    asm volatile("cp.async.ca.shared.global [%0], [%1], 16;" :: "r"(dst_smem), "l"(src));
}

// ============ kernel 1: [B,C,H,W] -> [N,C] transpose + row norms + deg=0 ============
__global__ __launch_bounds__(192) void transpose_kernel(const float* __restrict__ x) {
    int bh = blockIdx.x;            // b*64 + h, 256 blocks
    __shared__ float s[48][65];
    const float* src = x + (size_t)(bh >> 6) * 48 * 4096 + (bh & 63) * 64;
    for (int idx = threadIdx.x; idx < 48 * 64; idx += 192) {
        int c = idx >> 6, w = idx & 63;
        s[c][w] = src[c * 4096 + w];
    }
    __syncthreads();
    float* dst = g_xf + (size_t)bh * 64 * 48;
    for (int idx = threadIdx.x; idx < 48 * 64; idx += 192) {
        int w = idx / 48, c = idx - w * 48;
        dst[w * 48 + c] = s[c][w];
    }
    if (threadIdx.x < 64) {
        int w = threadIdx.x;
        float acc = 0.f;
#pragma unroll
        for (int c = 0; c < 48; c++) acc += s[c][w] * s[c][w];
        g_sq[bh * 64 + w] = acc;
        g_deg[bh * 64 + w] = 0;
    }
}

// ============ kernel 2: knn (top-9 smallest dist, lower-index ties) ============
// 256 blocks x 128 threads. Block owns 64 centers; 2 threads per center split
// the candidate sweep. Candidate tiles (64 rows) double-buffered via cp.async.
// Warp lanes = 32 different centers reading the same candidate row: broadcast LDS.
__global__ __launch_bounds__(128, 4) void knn_kernel() {
    __shared__ __align__(16) float stile[2][TILE * 48];  // 2 x 12.3KB
    __shared__ float ssq[2][TILE];
    __shared__ float smd[64 * 2 * KNN];                  // partial dists (merge)
    __shared__ int   smi[64 * 2 * KNN];                  // partial idxs  (merge)

    const int tid  = threadIdx.x;
    const int il   = tid & 63;
    const int part = tid >> 6;                            // 0 or 1
    const int i    = blockIdx.x * 64 + il;
    const int batch  = blockIdx.x >> 6;
    const int jbase  = batch << 12;
    const int jcount = (batch == 3) ? (BATCHSZ - 1) : BATCHSZ;  // exclude node 16383

    const u32 stile_a = (u32)__cvta_generic_to_shared(&stile[0][0]);

    // center features in registers (as fp32x2 pairs)
    u64 xi2[24];
    {
        const ulonglong2* xr = (const ulonglong2*)(g_xf + (size_t)i * CDIM);
#pragma unroll
        for (int c = 0; c < 12; c++) {
            ulonglong2 v = xr[c];
            xi2[2 * c] = v.x; xi2[2 * c + 1] = v.y;
        }
    }
    const float sqi = g_sq[i];
    const float INF = __int_as_float(0x7f800000);

    float d9[KNN]; int n9[KNN];
#pragma unroll
    for (int k = 0; k < KNN; k++) { d9[k] = 3.402823466e+38f; n9[k] = 0x7fffffff; }

    const float4* gsrc = (const float4*)(g_xf + (size_t)jbase * CDIM);

    // preload tile 0 (rows are always valid memory; ssq padded with INF)
    {
#pragma unroll
        for (int q = 0; q < 6; q++) {
            const int idx = tid + q * 128;                // float4 index 0..767
            cp16(stile_a + idx * 16, gsrc + idx);
        }
        asm volatile("cp.async.commit_group;");
        if (tid < TILE) ssq[0][tid] = g_sq[jbase + tid];  // tile0 rows always < jcount
    }

    const int ntiles = BATCHSZ / TILE;  // 64
    for (int t = 0; t < ntiles; t++) {
        __syncthreads();   // all threads done computing tile t-1 (buffers free)
        if (t + 1 < ntiles) {
            const int nb = (t + 1) & 1;
            const float4* s4 = gsrc + (size_t)(t + 1) * TILE * 12;
#pragma unroll
            for (int q = 0; q < 6; q++) {
                const int idx = tid + q * 128;
                cp16(stile_a + (nb * TILE * 48) * 4 + idx * 16, s4 + idx);
            }
            asm volatile("cp.async.commit_group;");
            if (tid < TILE) {
                const int jn = (t + 1) * TILE + tid;
                ssq[nb][tid] = (jn < jcount) ? g_sq[jbase + jn] : INF;
            }
            asm volatile("cp.async.wait_group 1;");
        } else {
            asm volatile("cp.async.wait_group 0;");
        }
        __syncthreads();   // tile t fully visible to everyone

        const int jt = t * TILE;
        const float* buf = &stile[t & 1][0];
        const float* sbq = &ssq[t & 1][0];

#define PROCESS(SS)                                                              \
        {                                                                        \
            const int _r = part + 2 * (SS);                                      \
            const ulonglong2* _xj = (const ulonglong2*)(buf + _r * 48);          \
            u64 _a0 = 0, _a1 = 0;                                                \
            _Pragma("unroll")                                                    \
            for (int _c = 0; _c < 12; _c += 2) {                                 \
                ulonglong2 _v0 = _xj[_c];                                        \
                ulonglong2 _v1 = _xj[_c + 1];                                    \
                _a0 = fma2(xi2[2 * _c],     _v0.x, _a0);                         \
                _a1 = fma2(xi2[2 * _c + 1], _v0.y, _a1);                         \
                _a0 = fma2(xi2[2 * _c + 2], _v1.x, _a0);                         \
                _a1 = fma2(xi2[2 * _c + 3], _v1.y, _a1);                         \
            }                                                                    \
            u64 _sum = add2(_a0, _a1);                                           \
            float _lo, _hi; unpack2(_sum, _lo, _hi);                             \
            float _dist = fmaf(_lo + _hi, -2.0f, sqi + sbq[_r]);                 \
            if (_dist < d9[8]) {                                                 \
                d9[8] = _dist; n9[8] = jbase + jt + _r;                          \
                _Pragma("unroll")                                                \
                for (int _k = 8; _k > 0; _k--) {                                 \
                    if (d9[_k] < d9[_k - 1]) {                                   \
                        float _td = d9[_k]; d9[_k] = d9[_k - 1]; d9[_k - 1] = _td; \
                        int   _ti = n9[_k]; n9[_k] = n9[_k - 1]; n9[_k - 1] = _ti; \
                    }                                                            \
                }                                                                \
            }                                                                    \
        }

#pragma unroll 8
        for (int ss = 0; ss < TILE / 2; ss++) PROCESS(ss)
#undef PROCESS
    }

    // publish partials
    {
        const int base = (il * 2 + part) * KNN;
#pragma unroll
        for (int k = 0; k < KNN; k++) { smd[base + k] = d9[k]; smi[base + k] = n9[k]; }
    }
    __syncthreads();

    // 2-way lexicographic merge by (dist, idx), done by part-0 threads
    if (part == 0) {
        if (i == NNODE - 1) {
            // node 16383: alone in batch 4 -> self + 8 lowest-index -inf ties (0..7)
            g_nbr[i * KNN + 0] = NNODE - 1;
#pragma unroll
            for (int k = 1; k < KNN; k++) g_nbr[i * KNN + k] = k - 1;
        } else {
            int p[2] = {0, 0};
            for (int k = 0; k < KNN; k++) {
                float bd = 3.402823466e+38f; int bi = 0x7fffffff; int bq = 0;
#pragma unroll
                for (int q = 0; q < 2; q++) {
                    const int pq = p[q];
                    float dq = 3.402823466e+38f; int iq = 0x7fffffff;
                    if (pq < KNN) {
                        dq = smd[(il * 2 + q) * KNN + pq];
                        iq = smi[(il * 2 + q) * KNN + pq];
                    }
                    if (dq < bd || (dq == bd && iq < bi)) { bd = dq; bi = iq; bq = q; }
                }
                p[bq]++;
                g_nbr[i * KNN + k] = bi;
            }
        }
    }
}

// ============ kernel 3: degree over src ============
__global__ __launch_bounds__(256) void deg_kernel() {
    int e = blockIdx.x * 256 + threadIdx.x;
    if (e < NNODE * KNN) atomicAdd(&g_deg[g_nbr[e]], 1);
}

// ============ kernel 3b: dinv = rsqrt(deg) ============
__global__ __launch_bounds__(256) void dinv_kernel() {
    int i = blockIdx.x * 256 + threadIdx.x;
    if (i < NNODE) g_dinv[i] = rsqrtf((float)g_deg[i]);
}

// ============ kernel 4: fused gather + (xf@W0 + tx1@W1 + b) + relu ============
// block = 384 threads = 8 rows x 48 output cols
__global__ __launch_bounds__(384) void out_kernel(const float* __restrict__ W0,
                                                  const float* __restrict__ W1,
                                                  const float* __restrict__ b,
                                                  float* __restrict__ out) {
    __shared__ float W0s[2304], W1s[2304], bs[48];
    __shared__ float sx[8][48], sg[8][48], sdin[8];
    const int tid = threadIdx.x;
    for (int k = tid; k < 2304; k += 384) { W0s[k] = W0[k]; W1s[k] = W1[k]; }
    if (tid < 48) bs[tid] = b[tid];

    const int row = tid / 48, o = tid % 48;
    const int i = blockIdx.x * 8 + row;

    sx[row][o] = g_xf[(size_t)i * 48 + o];
    float g = 0.f;
    const int* nb = &g_nbr[i * KNN];
#pragma unroll
    for (int k = 0; k < KNN; k++) {
        const int j = nb[k];
        g += g_dinv[j] * g_xf[(size_t)j * 48 + o];
    }
    sg[row][o] = g;
    if (o == 0) sdin[row] = g_dinv[i];
    __syncthreads();

    float a0 = 0.f, a1 = 0.f;
#pragma unroll
    for (int c = 0; c < 48; c++) {
        a0 += sx[row][c] * W0s[c * 48 + o];
        a1 += sg[row][c] * W1s[c * 48 + o];
    }
    const float v = bs[o] + a0 - sdin[row] * a1;
    out[(size_t)i * 48 + o] = fmaxf(v, 0.f);
}

// ============ launch ============
extern "C" void kernel_launch(void* const* d_in, const int* in_sizes, int n_in,
                              void* d_out, int out_size) {
    const float* x  = (const float*)d_in[0];
    const float* W0 = (const float*)d_in[1];
    const float* W1 = (const float*)d_in[2];
    const float* b  = (const float*)d_in[3];
    float* out = (float*)d_out;

    transpose_kernel<<<256, 192>>>(x);
    knn_kernel<<<256, 128>>>();
    deg_kernel<<<(NNODE * KNN + 255) / 256, 256>>>();
    dinv_kernel<<<NNODE / 256, 256>>>();
    out_kernel<<<NNODE / 8, 384>>>(W0, W1, b, out);
}

// round 8
// speedup vs baseline: 1.0837x; 1.0837x over previous
#include <cuda_runtime.h>
#include <cuda_bf16.h>
#include <cstdint>

#define NNODE   16384
#define CDIM    48
#define KNN     9
#define BATCHSZ 4096
#define TILE    64
#define HALF    2048
#define NTILES  32

typedef unsigned long long u64;
typedef unsigned int u32;

// -------- scratch (device globals; no allocation allowed) --------
__device__ __align__(256) float g_xf[NNODE * CDIM];   // [N,48] node features
__device__ float g_sq[NNODE];                         // row squared norms
__device__ float g_pd[NNODE * 2 * KNN];               // per-half top-9 dists
__device__ int   g_pi[NNODE * 2 * KNN];               // per-half top-9 idxs
__device__ int   g_nbr[NNODE * KNN];                  // knn indices
__device__ int   g_deg[NNODE];                        // degree over src
__device__ float g_dinv[NNODE];                       // rsqrt(deg)

__device__ __forceinline__ u64 fma2(u64 a, u64 b, u64 c) {
    u64 d;
    asm("fma.rn.f32x2 %0, %1, %2, %3;" : "=l"(d) : "l"(a), "l"(b), "l"(c));
    return d;
}
__device__ __forceinline__ u64 add2(u64 a, u64 b) {
    u64 d;
    asm("add.rn.f32x2 %0, %1, %2;" : "=l"(d) : "l"(a), "l"(b));
    return d;
}
__device__ __forceinline__ void unpack2(u64 v, float& lo, float& hi) {
    asm("mov.b64 {%0, %1}, %2;" : "=f"(lo), "=f"(hi) : "l"(v));
}
__device__ __forceinline__ void cp16(u32 dst_smem, const void* src) {
    asm volatile("cp.async.ca.shared.global [%0], [%1], 16;" :: "r"(dst_smem), "l"(src));
}

// ============ kernel 1: [B,C,H,W] -> [N,C] transpose + row norms + deg=0 ============
__global__ __launch_bounds__(192) void transpose_kernel(const float* __restrict__ x) {
    int bh = blockIdx.x;            // b*64 + h, 256 blocks
    __shared__ float s[48][65];
    const float* src = x + (size_t)(bh >> 6) * 48 * 4096 + (bh & 63) * 64;
    for (int idx = threadIdx.x; idx < 48 * 64; idx += 192) {
        int c = idx >> 6, w = idx & 63;
        s[c][w] = src[c * 4096 + w];
    }
    __syncthreads();
    float* dst = g_xf + (size_t)bh * 64 * 48;
    for (int idx = threadIdx.x; idx < 48 * 64; idx += 192) {
        int w = idx / 48, c = idx - w * 48;
        dst[w * 48 + c] = s[c][w];
    }
    if (threadIdx.x < 64) {
        int w = threadIdx.x;
        float acc = 0.f;
#pragma unroll
        for (int c = 0; c < 48; c++) acc += s[c][w] * s[c][w];
        g_sq[bh * 64 + w] = acc;
        g_deg[bh * 64 + w] = 0;
    }
}

// ============ kernel 2: knn partial (512 blocks x 128 thr) ============
// Block bid: center group g=bid>>1 (64 centers), sweep half h=bid&1 (2048 cands).
// 2 threads/center split rows within each 64-row tile; tiles double-buffered cp.async.
__global__ __launch_bounds__(128, 4) void knn_kernel() {
    __shared__ __align__(16) float stile[2][TILE * 48];  // 2 x 12.3KB
    __shared__ float ssq[2][TILE];
    __shared__ float smd[64 * 2 * KNN];
    __shared__ int   smi[64 * 2 * KNN];

    const int tid  = threadIdx.x;
    const int il   = tid & 63;
    const int part = tid >> 6;                            // 0 or 1
    const int grp  = blockIdx.x >> 1;
    const int h    = blockIdx.x & 1;
    const int i    = grp * 64 + il;
    const int batch  = grp >> 6;
    const int jbase  = batch << 12;
    const int jcount = (batch == 3) ? (BATCHSZ - 1) : BATCHSZ;  // exclude node 16383
    const int hoff   = h * HALF;

    const u32 stile_a = (u32)__cvta_generic_to_shared(&stile[0][0]);

    u64 xi2[24];
    {
        const ulonglong2* xr = (const ulonglong2*)(g_xf + (size_t)i * CDIM);
#pragma unroll
        for (int c = 0; c < 12; c++) {
            ulonglong2 v = xr[c];
            xi2[2 * c] = v.x; xi2[2 * c + 1] = v.y;
        }
    }
    const float sqi = g_sq[i];
    const float INF = __int_as_float(0x7f800000);

    float d9[KNN]; int n9[KNN];
#pragma unroll
    for (int k = 0; k < KNN; k++) { d9[k] = 3.402823466e+38f; n9[k] = 0x7fffffff; }

    const float4* gsrc = (const float4*)(g_xf + (size_t)(jbase + hoff) * CDIM);

    // preload tile 0 (rows always valid memory; ssq padded with INF)
    {
#pragma unroll
        for (int q = 0; q < 6; q++) {
            const int idx = tid + q * 128;
            cp16(stile_a + idx * 16, gsrc + idx);
        }
        asm volatile("cp.async.commit_group;");
        if (tid < TILE) ssq[0][tid] = (hoff + tid < jcount) ? g_sq[jbase + hoff + tid] : INF;
    }

    for (int t = 0; t < NTILES; t++) {
        __syncthreads();   // previous tile consumed
        if (t + 1 < NTILES) {
            const int nb = (t + 1) & 1;
            const float4* s4 = gsrc + (size_t)(t + 1) * TILE * 12;
#pragma unroll
            for (int q = 0; q < 6; q++) {
                const int idx = tid + q * 128;
                cp16(stile_a + (nb * TILE * 48) * 4 + idx * 16, s4 + idx);
            }
            asm volatile("cp.async.commit_group;");
            if (tid < TILE) {
                const int jn = hoff + (t + 1) * TILE + tid;
                ssq[nb][tid] = (jn < jcount) ? g_sq[jbase + jn] : INF;
            }
            asm volatile("cp.async.wait_group 1;");
        } else {
            asm volatile("cp.async.wait_group 0;");
        }
        __syncthreads();   // tile t visible

        const int jt = hoff + t * TILE;
        const float* buf = &stile[t & 1][0];
        const float* sbq = &ssq[t & 1][0];

#define PROCESS(SS)                                                              \
        {                                                                        \
            const int _r = part + 2 * (SS);                                      \
            const ulonglong2* _xj = (const ulonglong2*)(buf + _r * 48);          \
            u64 _a0 = 0, _a1 = 0;                                                \
            _Pragma("unroll")                                                    \
            for (int _c = 0; _c < 12; _c += 2) {                                 \
                ulonglong2 _v0 = _xj[_c];                                        \
                ulonglong2 _v1 = _xj[_c + 1];                                    \
                _a0 = fma2(xi2[2 * _c],     _v0.x, _a0);                         \
                _a1 = fma2(xi2[2 * _c + 1], _v0.y, _a1);                         \
                _a0 = fma2(xi2[2 * _c + 2], _v1.x, _a0);                         \
                _a1 = fma2(xi2[2 * _c + 3], _v1.y, _a1);                         \
            }                                                                    \
            u64 _sum = add2(_a0, _a1);                                           \
            float _lo, _hi; unpack2(_sum, _lo, _hi);                             \
            float _dist = fmaf(_lo + _hi, -2.0f, sqi + sbq[_r]);                 \
            if (_dist < d9[8]) {                                                 \
                d9[8] = _dist; n9[8] = jbase + jt + _r;                          \
                _Pragma("unroll")                                                \
                for (int _k = 8; _k > 0; _k--) {                                 \
                    if (d9[_k] < d9[_k - 1]) {                                   \
                        float _td = d9[_k]; d9[_k] = d9[_k - 1]; d9[_k - 1] = _td; \
                        int   _ti = n9[_k]; n9[_k] = n9[_k - 1]; n9[_k - 1] = _ti; \
                    }                                                            \
                }                                                                \
            }                                                                    \
        }

#pragma unroll 8
        for (int ss = 0; ss < TILE / 2; ss++) PROCESS(ss)
#undef PROCESS
    }

    // publish partials
    {
        const int base = (il * 2 + part) * KNN;
#pragma unroll
        for (int k = 0; k < KNN; k++) { smd[base + k] = d9[k]; smi[base + k] = n9[k]; }
    }
    __syncthreads();

    // 2-way lexicographic merge of the block's two parts -> per-half top-9
    if (part == 0) {
        int p[2] = {0, 0};
        float* pd = &g_pd[(size_t)(i * 2 + h) * KNN];
        int*   pi = &g_pi[(size_t)(i * 2 + h) * KNN];
        for (int k = 0; k < KNN; k++) {
            float bd = 3.402823466e+38f; int bi = 0x7fffffff; int bq = 0;
#pragma unroll
            for (int q = 0; q < 2; q++) {
                const int pq = p[q];
                float dq = 3.402823466e+38f; int iq = 0x7fffffff;
                if (pq < KNN) {
                    dq = smd[(il * 2 + q) * KNN + pq];
                    iq = smi[(il * 2 + q) * KNN + pq];
                }
                if (dq < bd || (dq == bd && iq < bi)) { bd = dq; bi = iq; bq = q; }
            }
            p[bq]++;
            pd[k] = bd; pi[k] = bi;
        }
    }
}

// ============ kernel 2c: merge halves -> final top-9 ============
__global__ __launch_bounds__(256) void merge9_kernel() {
    int i = blockIdx.x * 256 + threadIdx.x;
    if (i >= NNODE) return;
    if (i == NNODE - 1) {
        // node 16383: alone in batch 4 -> self + 8 lowest-index -inf ties (0..7)
        g_nbr[i * KNN + 0] = NNODE - 1;
#pragma unroll
        for (int k = 1; k < KNN; k++) g_nbr[i * KNN + k] = k - 1;
        return;
    }
    const float* d0 = &g_pd[(size_t)(i * 2) * KNN];
    const int*   i0 = &g_pi[(size_t)(i * 2) * KNN];
    const float* d1 = &g_pd[(size_t)(i * 2 + 1) * KNN];
    const int*   i1 = &g_pi[(size_t)(i * 2 + 1) * KNN];
    int p0 = 0, p1 = 0;
#pragma unroll
    for (int k = 0; k < KNN; k++) {
        float a = d0[p0], b = d1[p1];
        int ia = i0[p0], ib = i1[p1];
        bool take0 = (a < b) || (a == b && ia < ib);
        g_nbr[i * KNN + k] = take0 ? ia : ib;
        if (take0) p0++; else p1++;
    }
}

// ============ kernel 3: degree over src ============
__global__ __launch_bounds__(256) void deg_kernel() {
    int e = blockIdx.x * 256 + threadIdx.x;
    if (e < NNODE * KNN) atomicAdd(&g_deg[g_nbr[e]], 1);
}

// ============ kernel 3b: dinv = rsqrt(deg) ============
__global__ __launch_bounds__(256) void dinv_kernel() {
    int i = blockIdx.x * 256 + threadIdx.x;
    if (i < NNODE) g_dinv[i] = rsqrtf((float)g_deg[i]);
}

// ============ kernel 4: fused gather + (xf@W0 + tx1@W1 + b) + relu ============
__global__ __launch_bounds__(384) void out_kernel(const float* __restrict__ W0,
                                                  const float* __restrict__ W1,
                                                  const float* __restrict__ b,
                                                  float* __restrict__ out) {
    __shared__ float W0s[2304], W1s[2304], bs[48];
    __shared__ float sx[8][48], sg[8][48], sdin[8];
    const int tid = threadIdx.x;
    for (int k = tid; k < 2304; k += 384) { W0s[k] = W0[k]; W1s[k] = W1[k]; }
    if (tid < 48) bs[tid] = b[tid];

    const int row = tid / 48, o = tid % 48;
    const int i = blockIdx.x * 8 + row;

    sx[row][o] = g_xf[(size_t)i * 48 + o];
    float g = 0.f;
    const int* nb = &g_nbr[i * KNN];
#pragma unroll
    for (int k = 0; k < KNN; k++) {
        const int j = nb[k];
        g += g_dinv[j] * g_xf[(size_t)j * 48 + o];
    }
    sg[row][o] = g;
    if (o == 0) sdin[row] = g_dinv[i];
    __syncthreads();

    float a0 = 0.f, a1 = 0.f;
#pragma unroll
    for (int c = 0; c < 48; c++) {
        a0 += sx[row][c] * W0s[c * 48 + o];
        a1 += sg[row][c] * W1s[c * 48 + o];
    }
    const float v = bs[o] + a0 - sdin[row] * a1;
    out[(size_t)i * 48 + o] = fmaxf(v, 0.f);
}

// ============ launch ============
extern "C" void kernel_launch(void* const* d_in, const int* in_sizes, int n_in,
                              void* d_out, int out_size) {
    const float* x  = (const float*)d_in[0];
    const float* W0 = (const float*)d_in[1];
    const float* W1 = (const float*)d_in[2];
    const float* b  = (const float*)d_in[3];
    float* out = (float*)d_out;

    transpose_kernel<<<256, 192>>>(x);
    knn_kernel<<<512, 128>>>();
    merge9_kernel<<<NNODE / 256, 256>>>();
    deg_kernel<<<(NNODE * KNN + 255) / 256, 256>>>();
    dinv_kernel<<<NNODE / 256, 256>>>();
    out_kernel<<<NNODE / 8, 384>>>(W0, W1, b, out);
}